// round 3
// baseline (speedup 1.0000x reference)
#include <cuda_runtime.h>

#define B_ 8
#define N_ 16384
#define M_ 1024

// ---------------- scratch (no allocations allowed) ----------------
__device__ int   g_idx[B_*N_*3];          // 3-NN indices
__device__ float g_wt [B_*N_*3];          // 3-NN weights
__device__ float g_G  [B_*M_*256];        // G[b][m][o] = (w0[:, :256] @ source_feats[b])^T
__device__ float g_s0[256], g_bz0[256], g_s1[256], g_bz1[256];

// ---------------- BN param folding ----------------
__global__ void bn_prep_kernel(const float* __restrict__ g0, const float* __restrict__ b0,
                               const float* __restrict__ mu0, const float* __restrict__ var0,
                               const float* __restrict__ g1, const float* __restrict__ b1,
                               const float* __restrict__ mu1, const float* __restrict__ var1){
  int o = threadIdx.x;
  float s0 = g0[o] * rsqrtf(var0[o] + 1e-5f);
  g_s0[o] = s0; g_bz0[o] = b0[o] - mu0[o]*s0;
  float s1 = g1[o] * rsqrtf(var1[o] + 1e-5f);
  g_s1[o] = s1; g_bz1[o] = b1[o] - mu1[o]*s1;
}

// ---------------- 3-NN + interpolation weights ----------------
__global__ __launch_bounds__(256) void nn_kernel(const float* __restrict__ target,
                                                 const float* __restrict__ source){
  __shared__ float sx[M_], sy[M_], sz[M_];
  const int b = blockIdx.y;
  const int i = blockIdx.x*256 + threadIdx.x;
  for (int j = threadIdx.x; j < M_; j += 256){
    sx[j] = source[(b*M_ + j)*3 + 0];
    sy[j] = source[(b*M_ + j)*3 + 1];
    sz[j] = source[(b*M_ + j)*3 + 2];
  }
  __syncthreads();
  const float tx = target[((size_t)b*N_ + i)*3 + 0];
  const float ty = target[((size_t)b*N_ + i)*3 + 1];
  const float tz = target[((size_t)b*N_ + i)*3 + 2];
  float d0 = 3.4e38f, d1 = 3.4e38f, d2 = 3.4e38f;
  int   j0 = 0, j1 = 0, j2 = 0;
  for (int m = 0; m < M_; m++){
    float ddx = tx - sx[m], ddy = ty - sy[m], ddz = tz - sz[m];
    float d = ddx*ddx + ddy*ddy + ddz*ddz;   // same form as reference
    if (d < d2){
      if (d < d1){
        d2 = d1; j2 = j1;
        if (d < d0){ d1 = d0; j1 = j0; d0 = d; j0 = m; }
        else       { d1 = d;  j1 = m; }
      } else { d2 = d; j2 = m; }
    }
  }
  float r0 = 1.0f/(d0 + 1e-8f);
  float r1 = 1.0f/(d1 + 1e-8f);
  float r2 = 1.0f/(d2 + 1e-8f);
  float rs = r0 + r1 + r2;
  int base = (b*N_ + i)*3;
  g_idx[base+0] = j0; g_wt[base+0] = r0/rs;
  g_idx[base+1] = j1; g_wt[base+1] = r1/rs;
  g_idx[base+2] = j2; g_wt[base+2] = r2/rs;
}

// ---------------- G[b][m][o] = sum_c w0[o][c] * sf[b][c][m],  c in [0,256) ----------------
__global__ __launch_bounds__(256) void gemmG_kernel(const float* __restrict__ sf,
                                                    const float* __restrict__ w0){
  __shared__ float sfs[16][64];
  __shared__ float w0s[256][17];
  const int b   = blockIdx.y;
  const int m0  = blockIdx.x*64;
  const int tid = threadIdx.x;
  float acc[64];
  #pragma unroll
  for (int mm = 0; mm < 64; mm++) acc[mm] = 0.f;
  for (int ct = 0; ct < 16; ct++){
    {
      int r = tid*4;
      int cc = r >> 6, mm = r & 63;
      *(float4*)&sfs[cc][mm] =
        *(const float4*)&sf[((size_t)b*256 + ct*16 + cc)*M_ + m0 + mm];
      const float4* src = (const float4*)&w0[tid*384 + ct*16];
      float4 v0 = src[0], v1 = src[1], v2 = src[2], v3 = src[3];
      float* dst = w0s[tid];
      dst[0]=v0.x;  dst[1]=v0.y;  dst[2]=v0.z;  dst[3]=v0.w;
      dst[4]=v1.x;  dst[5]=v1.y;  dst[6]=v1.z;  dst[7]=v1.w;
      dst[8]=v2.x;  dst[9]=v2.y;  dst[10]=v2.z; dst[11]=v2.w;
      dst[12]=v3.x; dst[13]=v3.y; dst[14]=v3.z; dst[15]=v3.w;
    }
    __syncthreads();
    #pragma unroll
    for (int cc = 0; cc < 16; cc++){
      float wv = w0s[tid][cc];
      #pragma unroll
      for (int mm = 0; mm < 64; mm++) acc[mm] += wv * sfs[cc][mm];
    }
    __syncthreads();
  }
  #pragma unroll 8
  for (int mm = 0; mm < 64; mm++)
    g_G[((size_t)b*M_ + m0 + mm)*256 + tid] = acc[mm];
}

// ---------------- fused gather + layer0 + BN/ReLU + layer1 + BN/ReLU ----------------
// Block: 64 points x 256 channels. Thread microtile: 8 chan (stride 32) x 8 points.
// lane = channel group (og), warp = point group (ig) -> all smem B-reads broadcast,
// A-reads lane-consecutive, X1 pitch 65 -> conflict-free.
__global__ __launch_bounds__(256, 2) void fused_kernel(const float* __restrict__ tf,
                                                       const float* __restrict__ w0,
                                                       const float* __restrict__ w1,
                                                       float* __restrict__ out){
  extern __shared__ float smem[];
  float* Ts = smem;                    // [128][64]   target_feats tile
  float* Ws = Ts + 128*64;             // [8][256]    weight K-chunk (reused both layers)
  float* X1 = Ws + 8*256;              // [256][65]   layer-0 activations
  int*   Si = (int*)(X1 + 256*65);     // [64*3]
  float* Sw = (float*)(Si + 192);      // [64*3]

  const int b   = blockIdx.y;
  const int i0  = blockIdx.x*64;
  const int tid = threadIdx.x;
  const int og  = tid & 31;            // lane -> channel group
  const int ig  = tid >> 5;            // warp -> point group

  for (int r = tid; r < 128*16; r += 256){
    int c = r >> 4, q = r & 15;
    *(float4*)&Ts[c*64 + q*4] =
      *(const float4*)&tf[((size_t)(b*128 + c))*N_ + i0 + q*4];
  }
  if (tid < 192){
    Si[tid] = g_idx[(b*N_ + i0)*3 + tid];
    Sw[tid] = g_wt[(b*N_ + i0)*3 + tid];
  }
  __syncthreads();

  float acc[8][8];
  #pragma unroll
  for (int uo = 0; uo < 8; uo++)
    #pragma unroll
    for (int ui = 0; ui < 8; ui++) acc[uo][ui] = 0.f;

  // interpolation term: sum_j w_j * G[:, idx_j]   (G rows are L2-resident)
  #pragma unroll
  for (int j = 0; j < 3; j++){
    #pragma unroll
    for (int ui = 0; ui < 8; ui++){
      int p = (ig*8 + ui)*3 + j;
      int idx = Si[p];
      float w = Sw[p];
      const float* gp = &g_G[((size_t)b*M_ + idx)*256 + og];
      #pragma unroll
      for (int uo = 0; uo < 8; uo++)
        acc[uo][ui] = fmaf(w, gp[uo*32], acc[uo][ui]);
    }
  }

  // layer 0, target_feats part: K = 128 (w0 columns 256..383)
  for (int kt = 0; kt < 16; kt++){
    {
      const float4* wr = (const float4*)&w0[tid*384 + 256 + kt*8];
      float4 a0 = wr[0], a1 = wr[1];
      Ws[0*256+tid]=a0.x; Ws[1*256+tid]=a0.y; Ws[2*256+tid]=a0.z; Ws[3*256+tid]=a0.w;
      Ws[4*256+tid]=a1.x; Ws[5*256+tid]=a1.y; Ws[6*256+tid]=a1.z; Ws[7*256+tid]=a1.w;
    }
    __syncthreads();
    #pragma unroll
    for (int k = 0; k < 8; k++){
      float av[8], bv[8];
      #pragma unroll
      for (int uo = 0; uo < 8; uo++) av[uo] = Ws[k*256 + og + uo*32];
      float4 b0q = *(const float4*)&Ts[(kt*8 + k)*64 + ig*8];
      float4 b1q = *(const float4*)&Ts[(kt*8 + k)*64 + ig*8 + 4];
      bv[0]=b0q.x; bv[1]=b0q.y; bv[2]=b0q.z; bv[3]=b0q.w;
      bv[4]=b1q.x; bv[5]=b1q.y; bv[6]=b1q.z; bv[7]=b1q.w;
      #pragma unroll
      for (int uo = 0; uo < 8; uo++)
        #pragma unroll
        for (int ui = 0; ui < 8; ui++)
          acc[uo][ui] = fmaf(av[uo], bv[ui], acc[uo][ui]);
    }
    __syncthreads();
  }

  // BN0 + ReLU -> X1
  #pragma unroll
  for (int uo = 0; uo < 8; uo++){
    int o = og + uo*32;
    float s = g_s0[o], z = g_bz0[o];
    #pragma unroll
    for (int ui = 0; ui < 8; ui++)
      X1[o*65 + ig*8 + ui] = fmaxf(fmaf(acc[uo][ui], s, z), 0.f);
  }
  __syncthreads();

  // layer 1: K = 256
  #pragma unroll
  for (int uo = 0; uo < 8; uo++)
    #pragma unroll
    for (int ui = 0; ui < 8; ui++) acc[uo][ui] = 0.f;

  for (int kt = 0; kt < 32; kt++){
    {
      const float4* wr = (const float4*)&w1[tid*256 + kt*8];
      float4 a0 = wr[0], a1 = wr[1];
      Ws[0*256+tid]=a0.x; Ws[1*256+tid]=a0.y; Ws[2*256+tid]=a0.z; Ws[3*256+tid]=a0.w;
      Ws[4*256+tid]=a1.x; Ws[5*256+tid]=a1.y; Ws[6*256+tid]=a1.z; Ws[7*256+tid]=a1.w;
    }
    __syncthreads();
    #pragma unroll
    for (int k = 0; k < 8; k++){
      float av[8], bv[8];
      #pragma unroll
      for (int uo = 0; uo < 8; uo++) av[uo] = Ws[k*256 + og + uo*32];
      #pragma unroll
      for (int ui = 0; ui < 8; ui++) bv[ui] = X1[(kt*8 + k)*65 + ig*8 + ui];
      #pragma unroll
      for (int uo = 0; uo < 8; uo++)
        #pragma unroll
        for (int ui = 0; ui < 8; ui++)
          acc[uo][ui] = fmaf(av[uo], bv[ui], acc[uo][ui]);
    }
    __syncthreads();
  }

  // BN1 + ReLU -> out
  #pragma unroll
  for (int uo = 0; uo < 8; uo++){
    int o = og + uo*32;
    float s = g_s1[o], z = g_bz1[o];
    float v[8];
    #pragma unroll
    for (int ui = 0; ui < 8; ui++)
      v[ui] = fmaxf(fmaf(acc[uo][ui], s, z), 0.f);
    float* op = &out[((size_t)(b*256 + o))*N_ + i0 + ig*8];
    *(float4*)&op[0] = make_float4(v[0], v[1], v[2], v[3]);
    *(float4*)&op[4] = make_float4(v[4], v[5], v[6], v[7]);
  }
}

// ---------------- launch ----------------
extern "C" void kernel_launch(void* const* d_in, const int* in_sizes, int n_in,
                              void* d_out, int out_size){
  const float* target = (const float*)d_in[0];
  const float* source = (const float*)d_in[1];
  const float* tfeat  = (const float*)d_in[2];
  const float* sfeat  = (const float*)d_in[3];
  const float* w0     = (const float*)d_in[4];
  const float* g0     = (const float*)d_in[5];
  const float* b0     = (const float*)d_in[6];
  const float* mu0    = (const float*)d_in[7];
  const float* var0   = (const float*)d_in[8];
  const float* w1     = (const float*)d_in[9];
  const float* g1     = (const float*)d_in[10];
  const float* b1     = (const float*)d_in[11];
  const float* mu1    = (const float*)d_in[12];
  const float* var1   = (const float*)d_in[13];
  float* out = (float*)d_out;

  const int SMEM_FUSED = (128*64 + 8*256 + 256*65)*(int)sizeof(float)
                       + 192*(int)sizeof(int) + 192*(int)sizeof(float);
  cudaFuncSetAttribute(fused_kernel, cudaFuncAttributeMaxDynamicSharedMemorySize, SMEM_FUSED);

  bn_prep_kernel<<<1, 256>>>(g0, b0, mu0, var0, g1, b1, mu1, var1);
  nn_kernel<<<dim3(N_/256, B_), 256>>>(target, source);
  gemmG_kernel<<<dim3(M_/64, B_), 256>>>(sfeat, w0);
  fused_kernel<<<dim3(N_/64, B_), 256, SMEM_FUSED>>>(tfeat, w0, w1, out);
}

// round 9
// speedup vs baseline: 1.0083x; 1.0083x over previous
#include <cuda_runtime.h>

#define B_ 8
#define N_ 16384
#define M_ 1024

// ---------------- scratch (no allocations allowed) ----------------
__device__ int   g_idx[B_*N_*3];
__device__ float g_wt [B_*N_*3];
__device__ float g_G  [B_*M_*256];        // G[b][m][o] = (w0[:, :256] @ source_feats[b])^T
__device__ float g_s0[256], g_bz0[256], g_s1[256], g_bz1[256];

// ---------------- packed f32x2 helpers (FFMA2 only reachable via PTX) ----------------
__device__ __forceinline__ unsigned long long pk2(float lo, float hi){
  unsigned long long r;
  asm("mov.b64 %0, {%1, %2};" : "=l"(r) : "f"(lo), "f"(hi));
  return r;
}
__device__ __forceinline__ void upk2(float& lo, float& hi, unsigned long long v){
  asm("mov.b64 {%0, %1}, %2;" : "=f"(lo), "=f"(hi) : "l"(v));
}
__device__ __forceinline__ void ffma2(unsigned long long& d, unsigned long long a, unsigned long long b){
  asm("fma.rn.f32x2 %0, %1, %2, %0;" : "+l"(d) : "l"(a), "l"(b));
}

// ---------------- BN param folding ----------------
__global__ void bn_prep_kernel(const float* __restrict__ g0, const float* __restrict__ b0,
                               const float* __restrict__ mu0, const float* __restrict__ var0,
                               const float* __restrict__ g1, const float* __restrict__ b1,
                               const float* __restrict__ mu1, const float* __restrict__ var1){
  int o = threadIdx.x;
  float s0 = g0[o] * rsqrtf(var0[o] + 1e-5f);
  g_s0[o] = s0; g_bz0[o] = b0[o] - mu0[o]*s0;
  float s1 = g1[o] * rsqrtf(var1[o] + 1e-5f);
  g_s1[o] = s1; g_bz1[o] = b1[o] - mu1[o]*s1;
}

// ---------------- 3-NN + interpolation weights ----------------
__global__ __launch_bounds__(256) void nn_kernel(const float* __restrict__ target,
                                                 const float* __restrict__ source){
  __shared__ float sx[M_], sy[M_], sz[M_];
  const int b = blockIdx.y;
  const int i = blockIdx.x*256 + threadIdx.x;
  for (int j = threadIdx.x; j < M_; j += 256){
    sx[j] = source[(b*M_ + j)*3 + 0];
    sy[j] = source[(b*M_ + j)*3 + 1];
    sz[j] = source[(b*M_ + j)*3 + 2];
  }
  __syncthreads();
  const float tx = target[((size_t)b*N_ + i)*3 + 0];
  const float ty = target[((size_t)b*N_ + i)*3 + 1];
  const float tz = target[((size_t)b*N_ + i)*3 + 2];
  float d0 = 3.4e38f, d1 = 3.4e38f, d2 = 3.4e38f;
  int   j0 = 0, j1 = 0, j2 = 0;
  for (int m = 0; m < M_; m++){
    float ddx = tx - sx[m], ddy = ty - sy[m], ddz = tz - sz[m];
    float d = ddx*ddx + ddy*ddy + ddz*ddz;   // same form as reference
    if (d < d2){
      if (d < d1){
        d2 = d1; j2 = j1;
        if (d < d0){ d1 = d0; j1 = j0; d0 = d; j0 = m; }
        else       { d1 = d;  j1 = m; }
      } else { d2 = d; j2 = m; }
    }
  }
  float r0 = 1.0f/(d0 + 1e-8f);
  float r1 = 1.0f/(d1 + 1e-8f);
  float r2 = 1.0f/(d2 + 1e-8f);
  float rs = r0 + r1 + r2;
  int base = (b*N_ + i)*3;
  g_idx[base+0] = j0; g_wt[base+0] = r0/rs;
  g_idx[base+1] = j1; g_wt[base+1] = r1/rs;
  g_idx[base+2] = j2; g_wt[base+2] = r2/rs;
}

// ---------------- G[b][m][o] = sum_c w0[o][c] * sf[b][c][m],  c in [0,256) ----------------
__global__ __launch_bounds__(256) void gemmG_kernel(const float* __restrict__ sf,
                                                    const float* __restrict__ w0){
  __shared__ float sfs[16][64];      // rows 256B-aligned -> 64-bit LDS ok
  __shared__ float w0s[256][17];
  const int b   = blockIdx.y;
  const int m0  = blockIdx.x*64;
  const int tid = threadIdx.x;
  unsigned long long acc2[32];
  #pragma unroll
  for (int m2 = 0; m2 < 32; m2++) acc2[m2] = 0ull;
  for (int ct = 0; ct < 16; ct++){
    {
      int r = tid*4;
      int cc = r >> 6, mm = r & 63;
      *(float4*)&sfs[cc][mm] =
        *(const float4*)&sf[((size_t)b*256 + ct*16 + cc)*M_ + m0 + mm];
      const float4* src = (const float4*)&w0[tid*384 + ct*16];
      float4 v0 = src[0], v1 = src[1], v2 = src[2], v3 = src[3];
      float* dst = w0s[tid];
      dst[0]=v0.x;  dst[1]=v0.y;  dst[2]=v0.z;  dst[3]=v0.w;
      dst[4]=v1.x;  dst[5]=v1.y;  dst[6]=v1.z;  dst[7]=v1.w;
      dst[8]=v2.x;  dst[9]=v2.y;  dst[10]=v2.z; dst[11]=v2.w;
      dst[12]=v3.x; dst[13]=v3.y; dst[14]=v3.z; dst[15]=v3.w;
    }
    __syncthreads();
    #pragma unroll
    for (int cc = 0; cc < 16; cc++){
      float wv = w0s[tid][cc];
      unsigned long long w2 = pk2(wv, wv);
      #pragma unroll
      for (int m2 = 0; m2 < 32; m2++)
        ffma2(acc2[m2], w2, *(const unsigned long long*)&sfs[cc][2*m2]);
    }
    __syncthreads();
  }
  #pragma unroll 8
  for (int m2 = 0; m2 < 32; m2++){
    float lo, hi; upk2(lo, hi, acc2[m2]);
    g_G[((size_t)b*M_ + m0 + 2*m2    )*256 + tid] = lo;
    g_G[((size_t)b*M_ + m0 + 2*m2 + 1)*256 + tid] = hi;
  }
}

// ---------------- fused gather + layer0 + BN/ReLU + layer1 + BN/ReLU ----------------
// Block: 64 points x 256 channels. Thread microtile: 8 chan (stride 32) x 8 points,
// points packed in pairs into f32x2. lane = channel group (og), warp = point group (ig).
// X1 stored as u64 pairs, pitch 33 u64: writes hit bank-pair 2*og mod 32 (conflict-free
// per 16-lane phase of the split 64-bit store), reads are warp-uniform broadcast.
__global__ __launch_bounds__(256, 2) void fused_kernel(const float* __restrict__ tf,
                                                       const float* __restrict__ w0,
                                                       const float* __restrict__ w1,
                                                       float* __restrict__ out){
  extern __shared__ float smem[];
  float* Ts = smem;                                   // [128][64] target_feats tile (rows 256B aligned)
  float* Ws = Ts + 128*64;                            // [8][256]  weight K-chunk
  unsigned long long* X1u = (unsigned long long*)(Ws + 8*256);  // [256][33] u64 (8B aligned: 40960B offset)
  int*   Si = (int*)(X1u + 256*33);                   // [64*3]
  float* Sw = (float*)(Si + 192);                     // [64*3]

  const int b   = blockIdx.y;
  const int i0  = blockIdx.x*64;
  const int tid = threadIdx.x;
  const int og  = tid & 31;            // lane -> channel group
  const int ig  = tid >> 5;            // warp -> point group

  for (int r = tid; r < 128*16; r += 256){
    int c = r >> 4, q = r & 15;
    *(float4*)&Ts[c*64 + q*4] =
      *(const float4*)&tf[((size_t)(b*128 + c))*N_ + i0 + q*4];
  }
  if (tid < 192){
    Si[tid] = g_idx[(b*N_ + i0)*3 + tid];
    Sw[tid] = g_wt[(b*N_ + i0)*3 + tid];
  }
  __syncthreads();

  unsigned long long acc2[8][4];
  #pragma unroll
  for (int uo = 0; uo < 8; uo++)
    #pragma unroll
    for (int q = 0; q < 4; q++) acc2[uo][q] = 0ull;

  // interpolation term: sum_j w_j * G[:, idx_j]  (G rows L2-resident), point-pairs packed
  #pragma unroll
  for (int j = 0; j < 3; j++){
    #pragma unroll
    for (int q = 0; q < 4; q++){
      int p0 = (ig*8 + 2*q)*3 + j;
      int p1 = p0 + 3;
      unsigned long long wq = pk2(Sw[p0], Sw[p1]);
      const float* gp0 = &g_G[((size_t)b*M_ + Si[p0])*256 + og];
      const float* gp1 = &g_G[((size_t)b*M_ + Si[p1])*256 + og];
      #pragma unroll
      for (int uo = 0; uo < 8; uo++)
        ffma2(acc2[uo][q], wq, pk2(gp0[uo*32], gp1[uo*32]));
    }
  }

  // layer 0, target_feats part: K = 128 (w0 columns 256..383)
  for (int kt = 0; kt < 16; kt++){
    {
      const float4* wr = (const float4*)&w0[tid*384 + 256 + kt*8];
      float4 a0 = wr[0], a1 = wr[1];
      Ws[0*256+tid]=a0.x; Ws[1*256+tid]=a0.y; Ws[2*256+tid]=a0.z; Ws[3*256+tid]=a0.w;
      Ws[4*256+tid]=a1.x; Ws[5*256+tid]=a1.y; Ws[6*256+tid]=a1.z; Ws[7*256+tid]=a1.w;
    }
    __syncthreads();
    #pragma unroll
    for (int k = 0; k < 8; k++){
      unsigned long long av2[8];
      #pragma unroll
      for (int uo = 0; uo < 8; uo++){
        float a = Ws[k*256 + og + uo*32];
        av2[uo] = pk2(a, a);
      }
      unsigned long long bv2[4];
      #pragma unroll
      for (int q = 0; q < 4; q++)
        bv2[q] = *(const unsigned long long*)&Ts[(kt*8 + k)*64 + ig*8 + 2*q];
      #pragma unroll
      for (int uo = 0; uo < 8; uo++)
        #pragma unroll
        for (int q = 0; q < 4; q++)
          ffma2(acc2[uo][q], av2[uo], bv2[q]);
    }
    __syncthreads();
  }

  // BN0 + ReLU -> X1u (u64 pairs, pitch 33)
  #pragma unroll
  for (int uo = 0; uo < 8; uo++){
    int o = og + uo*32;
    float s = g_s0[o], z = g_bz0[o];
    #pragma unroll
    for (int q = 0; q < 4; q++){
      float lo, hi; upk2(lo, hi, acc2[uo][q]);
      lo = fmaxf(fmaf(lo, s, z), 0.f);
      hi = fmaxf(fmaf(hi, s, z), 0.f);
      X1u[o*33 + ig*4 + q] = pk2(lo, hi);
    }
  }
  __syncthreads();

  // layer 1: K = 256
  #pragma unroll
  for (int uo = 0; uo < 8; uo++)
    #pragma unroll
    for (int q = 0; q < 4; q++) acc2[uo][q] = 0ull;

  for (int kt = 0; kt < 32; kt++){
    {
      const float4* wr = (const float4*)&w1[tid*256 + kt*8];
      float4 a0 = wr[0], a1 = wr[1];
      Ws[0*256+tid]=a0.x; Ws[1*256+tid]=a0.y; Ws[2*256+tid]=a0.z; Ws[3*256+tid]=a0.w;
      Ws[4*256+tid]=a1.x; Ws[5*256+tid]=a1.y; Ws[6*256+tid]=a1.z; Ws[7*256+tid]=a1.w;
    }
    __syncthreads();
    #pragma unroll
    for (int k = 0; k < 8; k++){
      unsigned long long av2[8];
      #pragma unroll
      for (int uo = 0; uo < 8; uo++){
        float a = Ws[k*256 + og + uo*32];
        av2[uo] = pk2(a, a);
      }
      unsigned long long bv2[4];
      #pragma unroll
      for (int q = 0; q < 4; q++)
        bv2[q] = X1u[(kt*8 + k)*33 + ig*4 + q];
      #pragma unroll
      for (int uo = 0; uo < 8; uo++)
        #pragma unroll
        for (int q = 0; q < 4; q++)
          ffma2(acc2[uo][q], av2[uo], bv2[q]);
    }
    __syncthreads();
  }

  // BN1 + ReLU -> out
  #pragma unroll
  for (int uo = 0; uo < 8; uo++){
    int o = og + uo*32;
    float s = g_s1[o], z = g_bz1[o];
    float v[8];
    #pragma unroll
    for (int q = 0; q < 4; q++){
      float lo, hi; upk2(lo, hi, acc2[uo][q]);
      v[2*q  ] = fmaxf(fmaf(lo, s, z), 0.f);
      v[2*q+1] = fmaxf(fmaf(hi, s, z), 0.f);
    }
    float* op = &out[((size_t)(b*256 + o))*N_ + i0 + ig*8];
    *(float4*)&op[0] = make_float4(v[0], v[1], v[2], v[3]);
    *(float4*)&op[4] = make_float4(v[4], v[5], v[6], v[7]);
  }
}

// ---------------- launch ----------------
extern "C" void kernel_launch(void* const* d_in, const int* in_sizes, int n_in,
                              void* d_out, int out_size){
  const float* target = (const float*)d_in[0];
  const float* source = (const float*)d_in[1];
  const float* tfeat  = (const float*)d_in[2];
  const float* sfeat  = (const float*)d_in[3];
  const float* w0     = (const float*)d_in[4];
  const float* g0     = (const float*)d_in[5];
  const float* b0     = (const float*)d_in[6];
  const float* mu0    = (const float*)d_in[7];
  const float* var0   = (const float*)d_in[8];
  const float* w1     = (const float*)d_in[9];
  const float* g1     = (const float*)d_in[10];
  const float* b1     = (const float*)d_in[11];
  const float* mu1    = (const float*)d_in[12];
  const float* var1   = (const float*)d_in[13];
  float* out = (float*)d_out;

  const int SMEM_FUSED = (128*64 + 8*256)*(int)sizeof(float)
                       + 256*33*(int)sizeof(unsigned long long)
                       + 192*(int)sizeof(int) + 192*(int)sizeof(float);
  cudaFuncSetAttribute(fused_kernel, cudaFuncAttributeMaxDynamicSharedMemorySize, SMEM_FUSED);

  bn_prep_kernel<<<1, 256>>>(g0, b0, mu0, var0, g1, b1, mu1, var1);
  nn_kernel<<<dim3(N_/256, B_), 256>>>(target, source);
  gemmG_kernel<<<dim3(M_/64, B_), 256>>>(sfeat, w0);
  fused_kernel<<<dim3(N_/64, B_), 256, SMEM_FUSED>>>(tfeat, w0, w1, out);
}